// round 4
// baseline (speedup 1.0000x reference)
#include <cuda_runtime.h>

// Scratch (allocation-free rule: __device__ globals)
__device__ float g_obuf[128 * 32 * 256]; // attention output o (bt, c, l)
__device__ float g_hbuf[16 * 32 * 256];  // conv output h (b,c,l)
__device__ float g_hbn[16 * 32 * 256];   // BN+ReLU(h)

typedef unsigned long long ull;

__device__ __forceinline__ float ex2f(float x) {
    float y;
    asm("ex2.approx.ftz.f32 %0, %1;" : "=f"(y) : "f"(x));
    return y;
}
__device__ __forceinline__ ull pk(float a, float b) {
    ull r; asm("mov.b64 %0, {%1, %2};" : "=l"(r) : "f"(a), "f"(b)); return r;
}
__device__ __forceinline__ void upk(ull x, float& a, float& b) {
    asm("mov.b64 {%0, %1}, %2;" : "=f"(a), "=f"(b) : "l"(x));
}
__device__ __forceinline__ ull fma2(ull a, ull b, ull c) {
    ull r; asm("fma.rn.f32x2 %0, %1, %2, %3;" : "=l"(r) : "l"(a), "l"(b), "l"(c)); return r;
}
__device__ __forceinline__ ull mul2(ull a, ull b) {
    ull r; asm("mul.rn.f32x2 %0, %1, %2;" : "=l"(r) : "l"(a), "l"(b)); return r;
}
__device__ __forceinline__ ull add2(ull a, ull b) {
    ull r; asm("add.rn.f32x2 %0, %1, %2;" : "=l"(r) : "l"(a), "l"(b)); return r;
}
__device__ __forceinline__ float hsum(ull x) {
    float a, b; upk(x, a, b); return a + b;
}

// ---------------------------------------------------------------------------
// Kernel A: per (b,t,head-pair hp). 4 heads per block. 512 threads:
// thread = (tok, hgg of 2 heads). QKV proj -> K/V to smem (d-major m-pair
// interleaved) -> attention -> o to g_obuf. 2 blocks/SM.
// smem floats: kbuf 4096 | vbuf 4096 | wql,wkl,wvl 512 ea | bbl 48
// ---------------------------------------------------------------------------
__global__ void __launch_bounds__(512, 2) k_attn(
    const float* __restrict__ x,
    const float* __restrict__ qw, const float* __restrict__ qb,
    const float* __restrict__ kw, const float* __restrict__ kb,
    const float* __restrict__ vw, const float* __restrict__ vb)
{
    extern __shared__ float sm[];
    float* kbuf = sm;                  // [4 h][128 mp][8]
    float* vbuf = sm + 4096;
    float* wql = sm + 8192;            // rows hp*16..+15 of q_w
    float* wkl = wql + 512;
    float* wvl = wkl + 512;
    float* bbl = wvl + 512;            // [qb16|kb16|vb16]

    const int tid = threadIdx.x;
    const int tok = tid & 255;
    const int hgg = tid >> 8;          // 0 or 1: two heads each
    const int hp = blockIdx.x & 1;     // head pair-of-4 group
    const int t = (blockIdx.x >> 1) & 7;
    const int b = blockIdx.x >> 4;

    for (int i = tid; i < 512; i += 512) {
        int row = i >> 5, col = i & 31;
        int g = (hp * 16 + row) * 32 + col;
        wql[i] = qw[g]; wkl[i] = kw[g]; wvl[i] = vw[g];
    }
    if (tid < 16) {
        bbl[tid] = qb[hp * 16 + tid];
        bbl[16 + tid] = kb[hp * 16 + tid];
        bbl[32 + tid] = vb[hp * 16 + tid];
    }

    // x[b, c, t, tok] column (coalesced over tok)
    float xr[32];
    #pragma unroll
    for (int c = 0; c < 32; c++)
        xr[c] = x[((b * 32 + c) * 16 + t) * 256 + tok];

    __syncthreads();

    ull xp[16];
    #pragma unroll
    for (int i = 0; i < 16; i++) xp[i] = pk(xr[2 * i], xr[2 * i + 1]);

    const ulonglong2* wq2 = (const ulonglong2*)wql;  // row: 8 ull2
    const ulonglong2* wk2 = (const ulonglong2*)wkl;
    const ulonglong2* wv2 = (const ulonglong2*)wvl;

    const float QS = 0.5f * 1.4426950408889634f;
    ull qp[4];
    #pragma unroll
    for (int hh = 0; hh < 2; hh++) {
        const int hl = hgg * 2 + hh;   // local head 0..3
        float qv[4], kv[4], vv[4];
        #pragma unroll
        for (int j = 0; j < 4; j++) {
            const int co = hl * 4 + j;
            ull a0 = 0, a1 = 0, b0 = 0, b1 = 0, c0 = 0, c1 = 0;
            #pragma unroll
            for (int c4 = 0; c4 < 8; c4++) {
                ulonglong2 w = wq2[co * 8 + c4];
                a0 = fma2(xp[2 * c4], w.x, a0);
                a1 = fma2(xp[2 * c4 + 1], w.y, a1);
                w = wk2[co * 8 + c4];
                b0 = fma2(xp[2 * c4], w.x, b0);
                b1 = fma2(xp[2 * c4 + 1], w.y, b1);
                w = wv2[co * 8 + c4];
                c0 = fma2(xp[2 * c4], w.x, c0);
                c1 = fma2(xp[2 * c4 + 1], w.y, c1);
            }
            qv[j] = hsum(add2(a0, a1)) + bbl[co];
            kv[j] = hsum(add2(b0, b1)) + bbl[16 + co];
            vv[j] = hsum(add2(c0, c1)) + bbl[32 + co];
        }
        float qn = sqrtf(qv[0]*qv[0] + qv[1]*qv[1] + qv[2]*qv[2] + qv[3]*qv[3]);
        float qi = QS / fmaxf(qn, 1e-12f);
        qp[2 * hh]     = pk(qv[0] * qi, qv[1] * qi);
        qp[2 * hh + 1] = pk(qv[2] * qi, qv[3] * qi);

        float kn = sqrtf(kv[0]*kv[0] + kv[1]*kv[1] + kv[2]*kv[2] + kv[3]*kv[3]);
        float ki = 1.0f / fmaxf(kn, 1e-12f);
        float vn = sqrtf(vv[0]*vv[0] + vv[1]*vv[1] + vv[2]*vv[2] + vv[3]*vv[3]);
        float vi = 1.0f / fmaxf(vn, 1e-12f);

        const int base = hl * 1024 + (tok >> 1) * 8 + (tok & 1);
        #pragma unroll
        for (int d = 0; d < 4; d++) {
            kbuf[base + 2 * d] = kv[d] * ki;
            vbuf[base + 2 * d] = vv[d] * vi;
        }
    }
    __syncthreads();

    const int bt = b * 8 + t;
    #pragma unroll
    for (int hh = 0; hh < 2; hh++) {
        const int hl = hgg * 2 + hh;
        const ulonglong2* kb2 = (const ulonglong2*)(kbuf + hl * 1024);
        const ulonglong2* vb2 = (const ulonglong2*)(vbuf + hl * 1024);
        float q0, q1, q2, q3;
        upk(qp[2 * hh], q0, q1); upk(qp[2 * hh + 1], q2, q3);
        const ull Q0 = pk(q0, q0), Q1 = pk(q1, q1), Q2 = pk(q2, q2), Q3 = pk(q3, q3);

        ull pa0 = 0, pa1 = 0, pa2 = 0, pa3 = 0, ss = 0;
        #pragma unroll 4
        for (int mp = 0; mp < 128; mp++) {
            ulonglong2 KA = kb2[2 * mp];
            ulonglong2 KB = kb2[2 * mp + 1];
            ull sA = mul2(Q0, KA.x);
            ull sB = mul2(Q2, KB.x);
            sA = fma2(Q1, KA.y, sA);
            sB = fma2(Q3, KB.y, sB);
            ull s = add2(sA, sB);
            float s0, s1; upk(s, s0, s1);
            ull pp = pk(ex2f(s0), ex2f(s1));
            ulonglong2 VA = vb2[2 * mp];
            ulonglong2 VB = vb2[2 * mp + 1];
            ss = add2(ss, pp);
            pa0 = fma2(pp, VA.x, pa0);
            pa1 = fma2(pp, VA.y, pa1);
            pa2 = fma2(pp, VB.x, pa2);
            pa3 = fma2(pp, VB.y, pa3);
        }
        float inv = 1.0f / hsum(ss);
        const int h = hp * 4 + hl;            // global head
        const int cbase = (bt * 32 + h * 4) * 256 + tok;
        g_obuf[cbase]       = hsum(pa0) * inv;
        g_obuf[cbase + 256] = hsum(pa1) * inv;
        g_obuf[cbase + 512] = hsum(pa2) * inv;
        g_obuf[cbase + 768] = hsum(pa3) * inv;
    }
}

// ---------------------------------------------------------------------------
// Kernel A2: output projection xo = o @ m_w^T + m_b -> out[:, :, t, :].
// grid = 128 (b,t), 256 threads (tok).
// ---------------------------------------------------------------------------
__global__ void __launch_bounds__(256) k_oproj(
    const float* __restrict__ mw, const float* __restrict__ mb,
    float* __restrict__ out)
{
    __shared__ float wm[1024];
    __shared__ float mbs[32];
    const int tid = threadIdx.x;
    const int bt = blockIdx.x;
    const int t = bt & 7, b = bt >> 3;

    for (int i = tid; i < 1024; i += 256) wm[i] = mw[i];
    if (tid < 32) mbs[tid] = mb[tid];

    ull ov[16];
    #pragma unroll
    for (int i = 0; i < 16; i++) {
        float o0 = g_obuf[(bt * 32 + 2 * i) * 256 + tid];
        float o1 = g_obuf[(bt * 32 + 2 * i + 1) * 256 + tid];
        ov[i] = pk(o0, o1);
    }
    __syncthreads();

    const ull* wmu = (const ull*)wm;   // row co: 16 ull, warp-uniform reads
    #pragma unroll
    for (int co = 0; co < 32; co++) {
        ull a0 = 0, a1 = 0;
        #pragma unroll
        for (int i = 0; i < 16; i += 2) {
            a0 = fma2(ov[i],     wmu[co * 16 + i],     a0);
            a1 = fma2(ov[i + 1], wmu[co * 16 + i + 1], a1);
        }
        out[((b * 32 + co) * 9 + t) * 256 + tid] = hsum(add2(a0, a1)) + mbs[co];
    }
}

// ---------------------------------------------------------------------------
// Kernel B: conv (9,1) VALID + bias -> g_hbuf. con = [xo t=0..7 | pre].
// grid = (8 cog, 16 b), 256 threads (l). Each block: 4 output channels.
// ---------------------------------------------------------------------------
__global__ void __launch_bounds__(256) k_conv(
    const float* __restrict__ out, const float* __restrict__ pre,
    const float* __restrict__ cw, const float* __restrict__ cb)
{
    __shared__ float cws[1152];   // [(ci*9+kt)*4 + j]
    __shared__ float cbs[4];
    const int tid = threadIdx.x;
    const int cog = blockIdx.x;
    const int b = blockIdx.y;

    for (int s = tid; s < 1152; s += 256) {
        int j = s & 3;
        int cikt = s >> 2;
        cws[s] = cw[cog * 1152 + j * 288 + cikt];
    }
    if (tid < 4) cbs[tid] = cb[cog * 4 + tid];
    __syncthreads();

    float acc[4];
    #pragma unroll
    for (int j = 0; j < 4; j++) acc[j] = cbs[j];

    for (int ci = 0; ci < 32; ci++) {
        #pragma unroll
        for (int kt = 0; kt < 9; kt++) {
            float v = (kt < 8) ? out[((b * 32 + ci) * 9 + kt) * 256 + tid]
                               : pre[ci * 256 + tid];
            float4 w = *(const float4*)&cws[(ci * 9 + kt) * 4];
            acc[0] += v * w.x; acc[1] += v * w.y;
            acc[2] += v * w.z; acc[3] += v * w.w;
        }
    }
    #pragma unroll
    for (int j = 0; j < 4; j++)
        g_hbuf[(b * 32 + cog * 4 + j) * 256 + tid] = acc[j];
}

// ---------------------------------------------------------------------------
// Kernel C: BN batch stats per channel over (b,l)=4096, then apply BN+ReLU
// into g_hbn. grid = 32 blocks (c), 128 threads.
// ---------------------------------------------------------------------------
__global__ void __launch_bounds__(128) k_stats(
    const float* __restrict__ gamma, const float* __restrict__ beta)
{
    __shared__ float rs[128], rs2[128];
    __shared__ float s_sc, s_sh;
    const int c = blockIdx.x, tid = threadIdx.x;
    float s = 0.f, s2 = 0.f;
    for (int e = tid; e < 4096; e += 128) {
        float v = g_hbuf[(e >> 8) * 8192 + c * 256 + (e & 255)];
        s += v; s2 += v * v;
    }
    rs[tid] = s; rs2[tid] = s2;
    __syncthreads();
    for (int off = 64; off > 0; off >>= 1) {
        if (tid < off) { rs[tid] += rs[tid + off]; rs2[tid] += rs2[tid + off]; }
        __syncthreads();
    }
    if (tid == 0) {
        float mean = rs[0] * (1.0f / 4096.0f);
        float var = rs2[0] * (1.0f / 4096.0f) - mean * mean;
        float rstd = rsqrtf(var + 1e-5f);
        float sc = rstd * gamma[c];
        s_sc = sc;
        s_sh = beta[c] - mean * sc;
    }
    __syncthreads();
    float sc = s_sc, sh = s_sh;
    for (int e = tid; e < 4096; e += 128) {
        int idx = (e >> 8) * 8192 + c * 256 + (e & 255);
        g_hbn[idx] = fmaxf(g_hbuf[idx] * sc + sh, 0.f);
    }
}

// ---------------------------------------------------------------------------
// Kernel D: linear over l (256x256) on g_hbn, p = xo[:,:,2] - p -> out slot 8.
// grid = (8 l'-tiles, 16 b), 512 threads. Thread (cq, lane): 2 channels x 1 l'.
// lin_w tile in smem (stride 260 = 4*65 floats -> conflict-free LDS.128).
// h rows read straight from gmem (warp-uniform LDG.128, L1/L2 hits).
// ---------------------------------------------------------------------------
__global__ void __launch_bounds__(512) k_lin(
    const float* __restrict__ lw, const float* __restrict__ lb,
    float* __restrict__ out)
{
    extern __shared__ float lws[];     // [32][260]
    const int tid = threadIdx.x;
    const int lane = tid & 31, cq = tid >> 5;   // cq in [0,16)
    const int lt = blockIdx.x;
    const int b = blockIdx.y;

    for (int idx = tid; idx < 8192; idx += 512) {
        int r = idx >> 8, col = idx & 255;
        lws[r * 260 + col] = lw[(lt * 32 + r) * 256 + col];
    }
    __syncthreads();

    const int c0 = cq * 2;
    ull acc[2] = {0, 0};
    const ulonglong2* wrow = (const ulonglong2*)&lws[lane * 260];
    const ulonglong2* h0 = (const ulonglong2*)&g_hbn[(b * 32 + c0) * 256];
    const ulonglong2* h1 = (const ulonglong2*)&g_hbn[(b * 32 + c0 + 1) * 256];
    #pragma unroll 8
    for (int l4 = 0; l4 < 64; l4++) {
        ulonglong2 w = wrow[l4];
        ulonglong2 a = h0[l4], bq = h1[l4];
        acc[0] = fma2(w.x, a.x,  acc[0]); acc[0] = fma2(w.y, a.y,  acc[0]);
        acc[1] = fma2(w.x, bq.x, acc[1]); acc[1] = fma2(w.y, bq.y, acc[1]);
    }

    const int lp = lt * 32 + lane;
    const float lbv = lb[lp];
    #pragma unroll
    for (int j = 0; j < 2; j++) {
        int base = (b * 32 + c0 + j) * 9;
        float p = hsum(acc[j]) + lbv;
        out[(base + 8) * 256 + lp] = out[(base + 2) * 256 + lp] - p;
    }
}

// ---------------------------------------------------------------------------
extern "C" void kernel_launch(void* const* d_in, const int* in_sizes, int n_in,
                              void* d_out, int out_size)
{
    const float* x     = (const float*)d_in[0];
    const float* qw    = (const float*)d_in[1];
    const float* qb    = (const float*)d_in[2];
    const float* kw    = (const float*)d_in[3];
    const float* kb    = (const float*)d_in[4];
    const float* vw    = (const float*)d_in[5];
    const float* vb    = (const float*)d_in[6];
    const float* mw    = (const float*)d_in[7];
    const float* mb    = (const float*)d_in[8];
    const float* pre   = (const float*)d_in[9];
    const float* cw    = (const float*)d_in[10];
    const float* cb    = (const float*)d_in[11];
    const float* gamma = (const float*)d_in[12];
    const float* beta  = (const float*)d_in[13];
    const float* lw    = (const float*)d_in[14];
    const float* lb    = (const float*)d_in[15];
    float* out = (float*)d_out;

    const int smemA = (4096 + 4096 + 512 * 3 + 48) * 4;  // 39104 B
    cudaFuncSetAttribute(k_attn, cudaFuncAttributeMaxDynamicSharedMemorySize, smemA);
    const int smemD = (32 * 260) * 4;                    // 33280 B
    cudaFuncSetAttribute(k_lin, cudaFuncAttributeMaxDynamicSharedMemorySize, smemD);

    k_attn<<<256, 512, smemA>>>(x, qw, qb, kw, kb, vw, vb);
    k_oproj<<<128, 256>>>(mw, mb, out);
    k_conv<<<dim3(8, 16), 256>>>(out, pre, cw, cb);
    k_stats<<<32, 128>>>(gamma, beta);
    k_lin<<<dim3(8, 16), 512, smemD>>>(lw, lb, out);
}

// round 5
// speedup vs baseline: 1.1697x; 1.1697x over previous
#include <cuda_runtime.h>

// Scratch (allocation-free rule: __device__ globals)
__device__ float g_obuf[128 * 32 * 256]; // attention output o (bt, c, l)
__device__ float g_hbuf[16 * 32 * 256];  // conv output h (b,c,l)
__device__ float g_psum[32 * 16];        // BN partial sums  [c][b]
__device__ float g_psum2[32 * 16];       // BN partial sumsq [c][b]
__device__ unsigned g_barrier;           // grid barrier counter (reset by k_attn)

typedef unsigned long long ull;

__device__ __forceinline__ float ex2f(float x) {
    float y;
    asm("ex2.approx.ftz.f32 %0, %1;" : "=f"(y) : "f"(x));
    return y;
}
__device__ __forceinline__ ull pk(float a, float b) {
    ull r; asm("mov.b64 %0, {%1, %2};" : "=l"(r) : "f"(a), "f"(b)); return r;
}
__device__ __forceinline__ void upk(ull x, float& a, float& b) {
    asm("mov.b64 {%0, %1}, %2;" : "=f"(a), "=f"(b) : "l"(x));
}
__device__ __forceinline__ ull fma2(ull a, ull b, ull c) {
    ull r; asm("fma.rn.f32x2 %0, %1, %2, %3;" : "=l"(r) : "l"(a), "l"(b), "l"(c)); return r;
}
__device__ __forceinline__ ull mul2(ull a, ull b) {
    ull r; asm("mul.rn.f32x2 %0, %1, %2;" : "=l"(r) : "l"(a), "l"(b)); return r;
}
__device__ __forceinline__ ull add2(ull a, ull b) {
    ull r; asm("add.rn.f32x2 %0, %1, %2;" : "=l"(r) : "l"(a), "l"(b)); return r;
}
__device__ __forceinline__ float hsum(ull x) {
    float a, b; upk(x, a, b); return a + b;
}

// Software grid barrier for 128 co-resident blocks. Monotonic counter,
// reset to 0 by k_attn (prior kernel in the same stream) every launch.
__device__ __forceinline__ void gbar(unsigned target) {
    __threadfence();
    __syncthreads();
    if (threadIdx.x == 0) {
        atomicAdd(&g_barrier, 1u);
        volatile unsigned* p = &g_barrier;
        while (*p < target) __nanosleep(64);
    }
    __syncthreads();
}

// ---------------------------------------------------------------------------
// Kernel A: per (b,t,head-pair hp). 4 heads per block. 512 threads:
// thread = (tok, hgg of 2 heads). QKV proj -> K/V to smem (d-major m-pair
// interleaved) -> attention -> o to g_obuf. 2 blocks/SM.
// ---------------------------------------------------------------------------
__global__ void __launch_bounds__(512, 2) k_attn(
    const float* __restrict__ x,
    const float* __restrict__ qw, const float* __restrict__ qb,
    const float* __restrict__ kw, const float* __restrict__ kb,
    const float* __restrict__ vw, const float* __restrict__ vb)
{
    extern __shared__ float sm[];
    float* kbuf = sm;                  // [4 h][128 mp][8]
    float* vbuf = sm + 4096;
    float* wql = sm + 8192;            // rows hp*16..+15 of q_w
    float* wkl = wql + 512;
    float* wvl = wkl + 512;
    float* bbl = wvl + 512;            // [qb16|kb16|vb16]

    const int tid = threadIdx.x;
    const int tok = tid & 255;
    const int hgg = tid >> 8;          // 0 or 1: two heads each
    const int hp = blockIdx.x & 1;     // head group-of-4
    const int t = (blockIdx.x >> 1) & 7;
    const int b = blockIdx.x >> 4;

    if (blockIdx.x == 0 && tid == 0) g_barrier = 0;  // arm k_tail's barrier

    for (int i = tid; i < 512; i += 512) {
        int row = i >> 5, col = i & 31;
        int g = (hp * 16 + row) * 32 + col;
        wql[i] = qw[g]; wkl[i] = kw[g]; wvl[i] = vw[g];
    }
    if (tid < 16) {
        bbl[tid] = qb[hp * 16 + tid];
        bbl[16 + tid] = kb[hp * 16 + tid];
        bbl[32 + tid] = vb[hp * 16 + tid];
    }

    float xr[32];
    #pragma unroll
    for (int c = 0; c < 32; c++)
        xr[c] = x[((b * 32 + c) * 16 + t) * 256 + tok];

    __syncthreads();

    ull xp[16];
    #pragma unroll
    for (int i = 0; i < 16; i++) xp[i] = pk(xr[2 * i], xr[2 * i + 1]);

    const ulonglong2* wq2 = (const ulonglong2*)wql;
    const ulonglong2* wk2 = (const ulonglong2*)wkl;
    const ulonglong2* wv2 = (const ulonglong2*)wvl;

    const float QS = 0.5f * 1.4426950408889634f;
    ull qp[4];
    #pragma unroll
    for (int hh = 0; hh < 2; hh++) {
        const int hl = hgg * 2 + hh;   // local head 0..3
        float qv[4], kv[4], vv[4];
        #pragma unroll
        for (int j = 0; j < 4; j++) {
            const int co = hl * 4 + j;
            ull a0 = 0, a1 = 0, b0 = 0, b1 = 0, c0 = 0, c1 = 0;
            #pragma unroll
            for (int c4 = 0; c4 < 8; c4++) {
                ulonglong2 w = wq2[co * 8 + c4];
                a0 = fma2(xp[2 * c4], w.x, a0);
                a1 = fma2(xp[2 * c4 + 1], w.y, a1);
                w = wk2[co * 8 + c4];
                b0 = fma2(xp[2 * c4], w.x, b0);
                b1 = fma2(xp[2 * c4 + 1], w.y, b1);
                w = wv2[co * 8 + c4];
                c0 = fma2(xp[2 * c4], w.x, c0);
                c1 = fma2(xp[2 * c4 + 1], w.y, c1);
            }
            qv[j] = hsum(add2(a0, a1)) + bbl[co];
            kv[j] = hsum(add2(b0, b1)) + bbl[16 + co];
            vv[j] = hsum(add2(c0, c1)) + bbl[32 + co];
        }
        float qn = sqrtf(qv[0]*qv[0] + qv[1]*qv[1] + qv[2]*qv[2] + qv[3]*qv[3]);
        float qi = QS / fmaxf(qn, 1e-12f);
        qp[2 * hh]     = pk(qv[0] * qi, qv[1] * qi);
        qp[2 * hh + 1] = pk(qv[2] * qi, qv[3] * qi);

        float kn = sqrtf(kv[0]*kv[0] + kv[1]*kv[1] + kv[2]*kv[2] + kv[3]*kv[3]);
        float ki = 1.0f / fmaxf(kn, 1e-12f);
        float vn = sqrtf(vv[0]*vv[0] + vv[1]*vv[1] + vv[2]*vv[2] + vv[3]*vv[3]);
        float vi = 1.0f / fmaxf(vn, 1e-12f);

        const int base = hl * 1024 + (tok >> 1) * 8 + (tok & 1);
        #pragma unroll
        for (int d = 0; d < 4; d++) {
            kbuf[base + 2 * d] = kv[d] * ki;
            vbuf[base + 2 * d] = vv[d] * vi;
        }
    }
    __syncthreads();

    const int bt = b * 8 + t;
    #pragma unroll
    for (int hh = 0; hh < 2; hh++) {
        const int hl = hgg * 2 + hh;
        const ulonglong2* kb2 = (const ulonglong2*)(kbuf + hl * 1024);
        const ulonglong2* vb2 = (const ulonglong2*)(vbuf + hl * 1024);
        float q0, q1, q2, q3;
        upk(qp[2 * hh], q0, q1); upk(qp[2 * hh + 1], q2, q3);
        const ull Q0 = pk(q0, q0), Q1 = pk(q1, q1), Q2 = pk(q2, q2), Q3 = pk(q3, q3);

        ull pa0 = 0, pa1 = 0, pa2 = 0, pa3 = 0, ss = 0;
        #pragma unroll 4
        for (int mp = 0; mp < 128; mp++) {
            ulonglong2 KA = kb2[2 * mp];
            ulonglong2 KB = kb2[2 * mp + 1];
            ull s = mul2(Q0, KA.x);
            s = fma2(Q1, KA.y, s);
            s = fma2(Q2, KB.x, s);
            s = fma2(Q3, KB.y, s);
            float s0, s1; upk(s, s0, s1);
            ull pp = pk(ex2f(s0), ex2f(s1));
            ulonglong2 VA = vb2[2 * mp];
            ulonglong2 VB = vb2[2 * mp + 1];
            ss = add2(ss, pp);
            pa0 = fma2(pp, VA.x, pa0);
            pa1 = fma2(pp, VA.y, pa1);
            pa2 = fma2(pp, VB.x, pa2);
            pa3 = fma2(pp, VB.y, pa3);
        }
        float inv = 1.0f / hsum(ss);
        const int h = hp * 4 + hl;
        const int cbase = (bt * 32 + h * 4) * 256 + tok;
        g_obuf[cbase]       = hsum(pa0) * inv;
        g_obuf[cbase + 256] = hsum(pa1) * inv;
        g_obuf[cbase + 512] = hsum(pa2) * inv;
        g_obuf[cbase + 768] = hsum(pa3) * inv;
    }
}

// ---------------------------------------------------------------------------
// Kernel T: fused tail, 128 persistent blocks x 256 threads.
//  phase 1: oproj xo = o @ m_w^T + m_b -> out slots t=0..7   (block = bt)
//  [grid barrier]
//  phase 2: conv(9,1)+bias -> g_hbuf + BN partial sums        (block = cog,b)
//  [grid barrier]
//  phase 3: every block reduces stats deterministically -> smem scale/shift
//  phase 4: BN+ReLU staged to smem, linear over l, out slot 8 (block = lt,b)
// ---------------------------------------------------------------------------
__global__ void __launch_bounds__(256) k_tail(
    const float* __restrict__ mw, const float* __restrict__ mb,
    const float* __restrict__ pre,
    const float* __restrict__ cw, const float* __restrict__ cb,
    const float* __restrict__ gamma, const float* __restrict__ beta,
    const float* __restrict__ lw, const float* __restrict__ lb,
    float* __restrict__ out)
{
    extern __shared__ float smd[];
    __shared__ float sred[8][4], sred2[8][4];
    __shared__ float s_sc[32], s_sh[32];

    const int tid = threadIdx.x;
    const int bid = blockIdx.x;

    // ---- phase 1: output projection for (b,t) = bid ----
    {
        float* wm = smd;             // 1024
        const int bt = bid;
        const int t = bt & 7, b = bt >> 3;

        for (int i = tid; i < 1024; i += 256) wm[i] = mw[i];

        ull ov[16];
        #pragma unroll
        for (int i = 0; i < 16; i++) {
            float o0 = g_obuf[(bt * 32 + 2 * i) * 256 + tid];
            float o1 = g_obuf[(bt * 32 + 2 * i + 1) * 256 + tid];
            ov[i] = pk(o0, o1);
        }
        __syncthreads();

        const ull* wmu = (const ull*)wm;
        #pragma unroll
        for (int co = 0; co < 32; co++) {
            ull a0 = 0, a1 = 0;
            #pragma unroll
            for (int i = 0; i < 16; i += 2) {
                a0 = fma2(ov[i],     wmu[co * 16 + i],     a0);
                a1 = fma2(ov[i + 1], wmu[co * 16 + i + 1], a1);
            }
            out[((b * 32 + co) * 9 + t) * 256 + tid] = hsum(add2(a0, a1)) + mb[co];
        }
    }

    gbar(128);

    // ---- phase 2: conv + bias -> g_hbuf, partial BN sums ----
    {
        float* cws = smd;            // 1152: [(ci*9+kt)*4 + j]
        const int cog = bid & 7;
        const int b = bid >> 3;

        for (int s = tid; s < 1152; s += 256) {
            int j = s & 3, cikt = s >> 2;
            cws[s] = cw[(cog * 4 + j) * 288 + cikt];
        }
        __syncthreads();

        float acc[4];
        #pragma unroll
        for (int j = 0; j < 4; j++) acc[j] = cb[cog * 4 + j];

        for (int ci = 0; ci < 32; ci++) {
            #pragma unroll
            for (int kt = 0; kt < 9; kt++) {
                float v = (kt < 8) ? out[((b * 32 + ci) * 9 + kt) * 256 + tid]
                                   : pre[ci * 256 + tid];
                float4 w = *(const float4*)&cws[(ci * 9 + kt) * 4];
                acc[0] += v * w.x; acc[1] += v * w.y;
                acc[2] += v * w.z; acc[3] += v * w.w;
            }
        }
        const int lane = tid & 31, wd = tid >> 5;
        #pragma unroll
        for (int j = 0; j < 4; j++) {
            g_hbuf[(b * 32 + cog * 4 + j) * 256 + tid] = acc[j];
            float v = acc[j], v2 = v * v;
            #pragma unroll
            for (int off = 16; off > 0; off >>= 1) {
                v  += __shfl_down_sync(0xffffffffu, v,  off);
                v2 += __shfl_down_sync(0xffffffffu, v2, off);
            }
            if (lane == 0) { sred[wd][j] = v; sred2[wd][j] = v2; }
        }
        __syncthreads();
        if (tid < 4) {
            float s = 0.f, s2 = 0.f;
            #pragma unroll
            for (int w8 = 0; w8 < 8; w8++) { s += sred[w8][tid]; s2 += sred2[w8][tid]; }
            g_psum [(cog * 4 + tid) * 16 + b] = s;
            g_psum2[(cog * 4 + tid) * 16 + b] = s2;
        }
    }

    gbar(256);

    // ---- phase 3: every block computes all-channel scale/shift (fixed order) ----
    if (tid < 32) {
        float s = 0.f, s2 = 0.f;
        #pragma unroll
        for (int b8 = 0; b8 < 16; b8++) {
            s  += g_psum [tid * 16 + b8];
            s2 += g_psum2[tid * 16 + b8];
        }
        float mean = s * (1.0f / 4096.0f);
        float var = s2 * (1.0f / 4096.0f) - mean * mean;
        float rstd = rsqrtf(var + 1e-5f);
        float sc = rstd * gamma[tid];
        s_sc[tid] = sc;
        s_sh[tid] = beta[tid] - mean * sc;
    }
    __syncthreads();

    // ---- phase 4: linear over l, p = xo[:,:,2] - p -> out slot 8 ----
    {
        float* hbn = smd;            // [32][256]
        float* lws = smd + 8192;     // [32][260]
        const int lt = bid & 7;
        const int b = bid >> 3;

        #pragma unroll 4
        for (int idx = tid; idx < 8192; idx += 256) {
            int c = idx >> 8;
            float v = g_hbuf[(b * 32 + c) * 256 + (idx & 255)];
            hbn[idx] = fmaxf(v * s_sc[c] + s_sh[c], 0.f);
        }
        #pragma unroll 4
        for (int idx = tid; idx < 8192; idx += 256) {
            int r = idx >> 8, col = idx & 255;
            lws[r * 260 + col] = lw[(lt * 32 + r) * 256 + col];
        }
        __syncthreads();

        const int lane = tid & 31, cq = tid >> 5;   // cq in [0,8)
        const int c0 = cq * 4;
        ull acc[4] = {0, 0, 0, 0};
        const ulonglong2* wrow = (const ulonglong2*)&lws[lane * 260];
        const ulonglong2* h0 = (const ulonglong2*)&hbn[(c0 + 0) * 256];
        const ulonglong2* h1 = (const ulonglong2*)&hbn[(c0 + 1) * 256];
        const ulonglong2* h2 = (const ulonglong2*)&hbn[(c0 + 2) * 256];
        const ulonglong2* h3 = (const ulonglong2*)&hbn[(c0 + 3) * 256];
        #pragma unroll 8
        for (int l4 = 0; l4 < 64; l4++) {
            ulonglong2 w = wrow[l4];
            ulonglong2 a = h0[l4], bq = h1[l4], cc = h2[l4], d = h3[l4];
            acc[0] = fma2(w.x, a.x,  acc[0]); acc[0] = fma2(w.y, a.y,  acc[0]);
            acc[1] = fma2(w.x, bq.x, acc[1]); acc[1] = fma2(w.y, bq.y, acc[1]);
            acc[2] = fma2(w.x, cc.x, acc[2]); acc[2] = fma2(w.y, cc.y, acc[2]);
            acc[3] = fma2(w.x, d.x,  acc[3]); acc[3] = fma2(w.y, d.y,  acc[3]);
        }

        const int lp = lt * 32 + lane;
        const float lbv = lb[lp];
        #pragma unroll
        for (int j = 0; j < 4; j++) {
            int base = (b * 32 + c0 + j) * 9;
            float p = hsum(acc[j]) + lbv;
            out[(base + 8) * 256 + lp] = out[(base + 2) * 256 + lp] - p;
        }
    }
}

// ---------------------------------------------------------------------------
extern "C" void kernel_launch(void* const* d_in, const int* in_sizes, int n_in,
                              void* d_out, int out_size)
{
    const float* x     = (const float*)d_in[0];
    const float* qw    = (const float*)d_in[1];
    const float* qb    = (const float*)d_in[2];
    const float* kw    = (const float*)d_in[3];
    const float* kb    = (const float*)d_in[4];
    const float* vw    = (const float*)d_in[5];
    const float* vb    = (const float*)d_in[6];
    const float* mw    = (const float*)d_in[7];
    const float* mb    = (const float*)d_in[8];
    const float* pre   = (const float*)d_in[9];
    const float* cw    = (const float*)d_in[10];
    const float* cb    = (const float*)d_in[11];
    const float* gamma = (const float*)d_in[12];
    const float* beta  = (const float*)d_in[13];
    const float* lw    = (const float*)d_in[14];
    const float* lb    = (const float*)d_in[15];
    float* out = (float*)d_out;

    const int smemA = (4096 + 4096 + 512 * 3 + 48) * 4;  // 39104 B
    cudaFuncSetAttribute(k_attn, cudaFuncAttributeMaxDynamicSharedMemorySize, smemA);
    const int smemT = (8192 + 32 * 260) * 4;             // 66048 B
    cudaFuncSetAttribute(k_tail, cudaFuncAttributeMaxDynamicSharedMemorySize, smemT);

    k_attn<<<256, 512, smemA>>>(x, qw, qb, kw, kb, vw, vb);
    k_tail<<<128, 256, smemT>>>(mw, mb, pre, cw, cb, gamma, beta, lw, lb, out);
}